// round 7
// baseline (speedup 1.0000x reference)
#include <cuda_runtime.h>
#include <cuda_bf16.h>
#include <cstdint>
#include <math.h>

// Problem constants
#define B_  2
#define S_  4096
#define D_  1024
#define H_  16
#define HD_ 64
#define M_  512
#define L_  1024
#define HID_ 2816
#define NSTEP 8

// ---------------------------------------------------------------------------
// Scratch (device globals; no allocation allowed)
// ---------------------------------------------------------------------------
__device__ float g_allout[B_ * S_ * D_];
__device__ float g_a   [B_ * M_ * D_];
__device__ float g_hn  [B_ * M_ * D_];
__device__ float g_t1  [B_ * M_ * HID_];
__device__ float g_t3  [B_ * M_ * HID_];
__device__ float g_m2  [B_ * M_ * D_];
__device__ float g_q   [B_ * M_ * D_];
__device__ float g_k   [B_ * L_ * D_];
__device__ float g_v   [B_ * L_ * D_];

// ---------------------------------------------------------------------------
// Warp-level bf16 MMA (HMMA) helper — valid under compute_103 (non-'a') target
// ---------------------------------------------------------------------------
__device__ __forceinline__ void mma16816(float* c,
                                         uint32_t a0, uint32_t a1, uint32_t a2, uint32_t a3,
                                         uint32_t b0, uint32_t b1)
{
    asm volatile(
        "mma.sync.aligned.m16n8k16.row.col.f32.bf16.bf16.f32 "
        "{%0,%1,%2,%3}, {%4,%5,%6,%7}, {%8,%9}, {%0,%1,%2,%3};"
        : "+f"(c[0]), "+f"(c[1]), "+f"(c[2]), "+f"(c[3])
        : "r"(a0), "r"(a1), "r"(a2), "r"(a3), "r"(b0), "r"(b1));
}

// ---------------------------------------------------------------------------
// Split-bf16 GEMM on tensor cores.
// C[z][mat] = A[z] (rows x K, row-major) @ B[mat] (K x N, row-major), fp32 io.
// acc = Ah*Bh + Ah*Bl + Al*Bh  (bf16 hi/lo split, ~1e-5 rel err)
// Tile 128x128, BK=32, 256 threads (8 warps as 2M x 4N, warp tile 64x32).
// grid: (nmat * tilesN, rows/128, batch).
// ---------------------------------------------------------------------------
#define BK 32
#define AST 40                      // bf16 row stride (20 words: conflict-free)
#define A_HALF (128 * AST * 2)      // 10240 bytes per half (hi or lo)
#define GEMM_SMEM (4 * A_HALF)      // Ahi, Alo, Bhi, Blo = 40960 bytes

template <bool ACC>
__global__ __launch_bounds__(256, 2)
void mma_gemm_kernel(const float* __restrict__ A, long long aBatch,
                     const float* __restrict__ B0, const float* __restrict__ B1,
                     const float* __restrict__ B2,
                     float* __restrict__ C0, float* __restrict__ C1, float* __restrict__ C2,
                     long long cB0, long long cB1, long long cB2,
                     int K, int N, int tilesN)
{
    extern __shared__ char smem[];
    __nv_bfloat16* Ahi = (__nv_bfloat16*)smem;
    __nv_bfloat16* Alo = (__nv_bfloat16*)(smem + A_HALF);
    __nv_bfloat16* Bhi = (__nv_bfloat16*)(smem + 2 * A_HALF);
    __nv_bfloat16* Blo = (__nv_bfloat16*)(smem + 3 * A_HALF);

    const int tid = threadIdx.x;
    const int wid = tid >> 5, lane = tid & 31;
    const int wm = wid & 1, wn = wid >> 1;           // 2 x 4 warp grid
    const int r  = lane >> 2, qc = (lane & 3) * 2;   // fragment coords

    const int tn  = blockIdx.x % tilesN;
    const int mat = blockIdx.x / tilesN;
    const int bz  = blockIdx.z;
    const int m0  = blockIdx.y * 128;
    const int n0  = tn * 128;

    const float* Bm = (mat == 0) ? B0 : ((mat == 1) ? B1 : B2);
    float*       Cm = (mat == 0) ? C0 : ((mat == 1) ? C1 : C2);
    const long long cB = (mat == 0) ? cB0 : ((mat == 1) ? cB1 : cB2);

    const float* Ab = A + (long long)bz * aBatch + (long long)m0 * K;

    // Load thread mappings
    const int ar  = tid >> 1,  akb = (tid & 1) * 16;   // A: 128 rows x 32 k
    const int bn  = tid & 127, bkb = (tid >> 7) * 16;  // B: col per thread, 16 k

    float4 pa[4];
    float  pb[16];

    // Preload chunk 0
    {
        const float* Ap = Ab + (size_t)ar * K + akb;
        #pragma unroll
        for (int j = 0; j < 4; j++) pa[j] = *(const float4*)(Ap + j * 4);
        const float* Bp = Bm + (size_t)bkb * N + n0 + bn;
        #pragma unroll
        for (int j = 0; j < 16; j++) pb[j] = Bp[(size_t)j * N];
    }

    float acc[4][4][4];
    #pragma unroll
    for (int i = 0; i < 4; i++)
        #pragma unroll
        for (int j = 0; j < 4; j++)
            #pragma unroll
            for (int e = 0; e < 4; e++) acc[i][j][e] = 0.f;

    const int NC = K / BK;
    #pragma unroll 1
    for (int kc = 0; kc < NC; kc++) {
        // ---- convert + store current chunk to smem ----
        #pragma unroll
        for (int j = 0; j < 4; j++) {
            float4 v = pa[j];
            __nv_bfloat16 h0 = __float2bfloat16(v.x);
            __nv_bfloat16 h1 = __float2bfloat16(v.y);
            __nv_bfloat16 h2 = __float2bfloat16(v.z);
            __nv_bfloat16 h3 = __float2bfloat16(v.w);
            __nv_bfloat162 hp0 = __halves2bfloat162(h0, h1);
            __nv_bfloat162 hp1 = __halves2bfloat162(h2, h3);
            __nv_bfloat162 lp0 = __floats2bfloat162_rn(v.x - __bfloat162float(h0),
                                                       v.y - __bfloat162float(h1));
            __nv_bfloat162 lp1 = __floats2bfloat162_rn(v.z - __bfloat162float(h2),
                                                       v.w - __bfloat162float(h3));
            int off = ar * AST + akb + j * 4;
            *(uint2*)&Ahi[off] = make_uint2(*(uint32_t*)&hp0, *(uint32_t*)&hp1);
            *(uint2*)&Alo[off] = make_uint2(*(uint32_t*)&lp0, *(uint32_t*)&lp1);
        }
        #pragma unroll
        for (int g = 0; g < 4; g++) {
            __nv_bfloat16 h0 = __float2bfloat16(pb[g * 4 + 0]);
            __nv_bfloat16 h1 = __float2bfloat16(pb[g * 4 + 1]);
            __nv_bfloat16 h2 = __float2bfloat16(pb[g * 4 + 2]);
            __nv_bfloat16 h3 = __float2bfloat16(pb[g * 4 + 3]);
            __nv_bfloat162 hp0 = __halves2bfloat162(h0, h1);
            __nv_bfloat162 hp1 = __halves2bfloat162(h2, h3);
            __nv_bfloat162 lp0 = __floats2bfloat162_rn(pb[g*4+0] - __bfloat162float(h0),
                                                       pb[g*4+1] - __bfloat162float(h1));
            __nv_bfloat162 lp1 = __floats2bfloat162_rn(pb[g*4+2] - __bfloat162float(h2),
                                                       pb[g*4+3] - __bfloat162float(h3));
            int off = bn * AST + bkb + g * 4;
            *(uint2*)&Bhi[off] = make_uint2(*(uint32_t*)&hp0, *(uint32_t*)&hp1);
            *(uint2*)&Blo[off] = make_uint2(*(uint32_t*)&lp0, *(uint32_t*)&lp1);
        }
        __syncthreads();

        // ---- prefetch next chunk (LDG latency overlaps MMA below) ----
        if (kc + 1 < NC) {
            const int k0n = (kc + 1) * BK;
            const float* Ap = Ab + (size_t)ar * K + k0n + akb;
            #pragma unroll
            for (int j = 0; j < 4; j++) pa[j] = *(const float4*)(Ap + j * 4);
            const float* Bp = Bm + (size_t)(k0n + bkb) * N + n0 + bn;
            #pragma unroll
            for (int j = 0; j < 16; j++) pb[j] = Bp[(size_t)j * N];
        }

        // ---- MMA over this chunk: 2 k-steps of 16 ----
        #pragma unroll
        for (int ks = 0; ks < 2; ks++) {
            const int kb = ks * 16;
            uint32_t bhf[4][2], blf[4][2];
            #pragma unroll
            for (int nt = 0; nt < 4; nt++) {
                int nb = (wn * 32 + nt * 8 + r) * AST + kb + qc;
                bhf[nt][0] = *(const uint32_t*)&Bhi[nb];
                bhf[nt][1] = *(const uint32_t*)&Bhi[nb + 8];
                blf[nt][0] = *(const uint32_t*)&Blo[nb];
                blf[nt][1] = *(const uint32_t*)&Blo[nb + 8];
            }
            #pragma unroll
            for (int mt = 0; mt < 4; mt++) {
                int rb = (wm * 64 + mt * 16 + r) * AST + kb + qc;
                uint32_t ah0 = *(const uint32_t*)&Ahi[rb];
                uint32_t ah1 = *(const uint32_t*)&Ahi[rb + 8 * AST];
                uint32_t ah2 = *(const uint32_t*)&Ahi[rb + 8];
                uint32_t ah3 = *(const uint32_t*)&Ahi[rb + 8 * AST + 8];
                uint32_t al0 = *(const uint32_t*)&Alo[rb];
                uint32_t al1 = *(const uint32_t*)&Alo[rb + 8 * AST];
                uint32_t al2 = *(const uint32_t*)&Alo[rb + 8];
                uint32_t al3 = *(const uint32_t*)&Alo[rb + 8 * AST + 8];
                #pragma unroll
                for (int nt = 0; nt < 4; nt++) {
                    mma16816(acc[mt][nt], ah0, ah1, ah2, ah3, bhf[nt][0], bhf[nt][1]);
                    mma16816(acc[mt][nt], ah0, ah1, ah2, ah3, blf[nt][0], blf[nt][1]);
                    mma16816(acc[mt][nt], al0, al1, al2, al3, bhf[nt][0], bhf[nt][1]);
                }
            }
        }
        __syncthreads();
    }

    // ---- epilogue ----
    float* Cb = Cm + (long long)bz * cB;
    #pragma unroll
    for (int mt = 0; mt < 4; mt++) {
        int row0 = m0 + wm * 64 + mt * 16 + r;
        #pragma unroll
        for (int nt = 0; nt < 4; nt++) {
            int col = n0 + wn * 32 + nt * 8 + qc;
            float* p0 = Cb + (size_t)row0 * N + col;
            float* p1 = Cb + (size_t)(row0 + 8) * N + col;
            float2 v0 = make_float2(acc[mt][nt][0], acc[mt][nt][1]);
            float2 v1 = make_float2(acc[mt][nt][2], acc[mt][nt][3]);
            if (ACC) {
                float2 o0 = *(const float2*)p0;
                float2 o1 = *(const float2*)p1;
                v0.x += o0.x; v0.y += o0.y;
                v1.x += o1.x; v1.y += o1.y;
            }
            *(float2*)p0 = v0;
            *(float2*)p1 = v1;
        }
    }
}

// ---------------------------------------------------------------------------
// RMSNorm
// ---------------------------------------------------------------------------
__global__ __launch_bounds__(256)
void rmsnorm_kernel(const float* __restrict__ x, const float* __restrict__ w,
                    float* __restrict__ o)
{
    const int row = blockIdx.x;
    const int tid = threadIdx.x;
    const float4 v = *(const float4*)(x + (size_t)row * D_ + tid * 4);
    float ss = v.x * v.x + v.y * v.y + v.z * v.z + v.w * v.w;
    #pragma unroll
    for (int off = 16; off; off >>= 1)
        ss += __shfl_xor_sync(0xffffffffu, ss, off);
    __shared__ float ws[8];
    __shared__ float s_inv;
    if ((tid & 31) == 0) ws[tid >> 5] = ss;
    __syncthreads();
    if (tid == 0) {
        float t = 0.f;
        #pragma unroll
        for (int i = 0; i < 8; i++) t += ws[i];
        s_inv = rsqrtf(t * (1.0f / D_) + 1e-5f);
    }
    __syncthreads();
    const float inv = s_inv;
    const float4 wv = *(const float4*)(w + tid * 4);
    float4 ov;
    ov.x = v.x * inv * wv.x;
    ov.y = v.y * inv * wv.y;
    ov.z = v.z * inv * wv.z;
    ov.w = v.w * inv * wv.w;
    *(float4*)(o + (size_t)row * D_ + tid * 4) = ov;
}

// ---------------------------------------------------------------------------
// SwiGLU gate
// ---------------------------------------------------------------------------
__global__ void silu_gate_kernel(float* __restrict__ t1,
                                 const float* __restrict__ t3, int n)
{
    int i = blockIdx.x * blockDim.x + threadIdx.x;
    if (i < n) {
        float a = t1[i];
        float s = a / (1.f + __expf(-a));
        t1[i] = s * t3[i];
    }
}

// ---------------------------------------------------------------------------
// RoPE
// ---------------------------------------------------------------------------
__global__ void rope_kernel(float* __restrict__ t,
                            const float* __restrict__ cosT,
                            const float* __restrict__ sinT,
                            int rowsPerB, int posOff, int nPairs)
{
    int id = blockIdx.x * blockDim.x + threadIdx.x;
    if (id >= nPairs) return;
    int pair = id & 511;
    int row  = id >> 9;
    int pos  = posOff + (row % rowsPerB);
    int i    = pair & 31;
    float c = cosT[pos * 32 + i];
    float s = sinT[pos * 32 + i];
    float2* p = (float2*)(t + (size_t)row * D_ + pair * 2);
    float2 v = *p;
    float2 o;
    o.x = v.x * c - v.y * s;
    o.y = v.x * s + v.y * c;
    *p = o;
}

// ---------------------------------------------------------------------------
// Flash-style causal attention (x-part queries only)
// ---------------------------------------------------------------------------
#define ALD 65
#define ATTN_SMEM ((4 * 64 * ALD + 3 * 64) * (int)sizeof(float))

__global__ __launch_bounds__(256)
void attn_kernel(const float* __restrict__ Q, const float* __restrict__ Kt,
                 const float* __restrict__ V, float* __restrict__ Out,
                 int outRowOff)
{
    extern __shared__ float sm[];
    float* Qs   = sm;
    float* Ks   = Qs + 64 * ALD;
    float* Vs   = Ks + 64 * ALD;
    float* Ss   = Vs + 64 * ALD;
    float* mrow = Ss + 64 * ALD;
    float* lrow = mrow + 64;
    float* crow = lrow + 64;

    const int b  = blockIdx.z;
    const int h  = blockIdx.y;
    const int qt = blockIdx.x;
    const int tid = threadIdx.x;
    const int tx = tid & 15, ty = tid >> 4;
    const int q0 = qt * 64;
    const float scale = 0.125f;

    for (int e = tid; e < 64 * 16; e += 256) {
        int i = e >> 4, d4 = (e & 15) * 4;
        float4 v = *(const float4*)&Q[((size_t)(b * M_ + q0 + i)) * D_ + h * HD_ + d4];
        Qs[i * ALD + d4 + 0] = v.x;
        Qs[i * ALD + d4 + 1] = v.y;
        Qs[i * ALD + d4 + 2] = v.z;
        Qs[i * ALD + d4 + 3] = v.w;
    }
    if (tid < 64) { mrow[tid] = -1e30f; lrow[tid] = 0.f; }
    float acc[4][4];
    #pragma unroll
    for (int i = 0; i < 4; i++)
        #pragma unroll
        for (int j = 0; j < 4; j++) acc[i][j] = 0.f;
    __syncthreads();

    const int nkt = qt + 9;
    for (int kt = 0; kt < nkt; kt++) {
        for (int e = tid; e < 64 * 16; e += 256) {
            int j = e >> 4, d4 = (e & 15) * 4;
            size_t base = ((size_t)(b * L_ + kt * 64 + j)) * D_ + h * HD_ + d4;
            float4 kv = *(const float4*)&Kt[base];
            Ks[j * ALD + d4 + 0] = kv.x;
            Ks[j * ALD + d4 + 1] = kv.y;
            Ks[j * ALD + d4 + 2] = kv.z;
            Ks[j * ALD + d4 + 3] = kv.w;
            float4 vv = *(const float4*)&V[base];
            Vs[j * ALD + d4 + 0] = vv.x;
            Vs[j * ALD + d4 + 1] = vv.y;
            Vs[j * ALD + d4 + 2] = vv.z;
            Vs[j * ALD + d4 + 3] = vv.w;
        }
        __syncthreads();

        float s4[4][4];
        #pragma unroll
        for (int i = 0; i < 4; i++)
            #pragma unroll
            for (int j = 0; j < 4; j++) s4[i][j] = 0.f;
        for (int d = 0; d < 64; d++) {
            float rq[4], rk[4];
            #pragma unroll
            for (int ii = 0; ii < 4; ii++) rq[ii] = Qs[(ty * 4 + ii) * ALD + d];
            #pragma unroll
            for (int jj = 0; jj < 4; jj++) rk[jj] = Ks[(tx * 4 + jj) * ALD + d];
            #pragma unroll
            for (int ii = 0; ii < 4; ii++)
                #pragma unroll
                for (int jj = 0; jj < 4; jj++)
                    s4[ii][jj] = fmaf(rq[ii], rk[jj], s4[ii][jj]);
        }
        const int qg0 = M_ + q0;
        #pragma unroll
        for (int ii = 0; ii < 4; ii++) {
            int qi = qg0 + ty * 4 + ii;
            #pragma unroll
            for (int jj = 0; jj < 4; jj++) {
                int kj = kt * 64 + tx * 4 + jj;
                float val = (kj <= qi) ? s4[ii][jj] * scale : -1e30f;
                Ss[(ty * 4 + ii) * ALD + tx * 4 + jj] = val;
            }
        }
        __syncthreads();

        if (tid < 64) {
            float mold = mrow[tid];
            float mx = mold;
            for (int j = 0; j < 64; j++) mx = fmaxf(mx, Ss[tid * ALD + j]);
            float c = __expf(mold - mx);
            float sum = 0.f;
            for (int j = 0; j < 64; j++) {
                float p = __expf(Ss[tid * ALD + j] - mx);
                Ss[tid * ALD + j] = p;
                sum += p;
            }
            mrow[tid] = mx;
            lrow[tid] = lrow[tid] * c + sum;
            crow[tid] = c;
        }
        __syncthreads();

        float cc[4];
        #pragma unroll
        for (int ii = 0; ii < 4; ii++) cc[ii] = crow[ty * 4 + ii];
        #pragma unroll
        for (int ii = 0; ii < 4; ii++)
            #pragma unroll
            for (int dd = 0; dd < 4; dd++) acc[ii][dd] *= cc[ii];
        for (int j = 0; j < 64; j++) {
            float rp[4], rv[4];
            #pragma unroll
            for (int ii = 0; ii < 4; ii++) rp[ii] = Ss[(ty * 4 + ii) * ALD + j];
            #pragma unroll
            for (int dd = 0; dd < 4; dd++) rv[dd] = Vs[j * ALD + tx * 4 + dd];
            #pragma unroll
            for (int ii = 0; ii < 4; ii++)
                #pragma unroll
                for (int dd = 0; dd < 4; dd++)
                    acc[ii][dd] = fmaf(rp[ii], rv[dd], acc[ii][dd]);
        }
        __syncthreads();
    }

    if (tid < 64) crow[tid] = 1.f / lrow[tid];
    __syncthreads();
    #pragma unroll
    for (int ii = 0; ii < 4; ii++) {
        float inv = crow[ty * 4 + ii];
        int grow = b * S_ + outRowOff + q0 + ty * 4 + ii;
        float4 o;
        o.x = acc[ii][0] * inv;
        o.y = acc[ii][1] * inv;
        o.z = acc[ii][2] * inv;
        o.w = acc[ii][3] * inv;
        *(float4*)&Out[(size_t)grow * D_ + h * HD_ + tx * 4] = o;
    }
}

// ---------------------------------------------------------------------------
// Launch
// ---------------------------------------------------------------------------
extern "C" void kernel_launch(void* const* d_in, const int* in_sizes, int n_in,
                              void* d_out, int out_size)
{
    const float* x        = (const float*)d_in[0];
    const float* cosT     = (const float*)d_in[1];
    const float* sinT     = (const float*)d_in[2];
    const float* wq       = (const float*)d_in[3];
    const float* wk       = (const float*)d_in[4];
    const float* wv       = (const float*)d_in[5];
    const float* wo       = (const float*)d_in[6];
    const float* wm       = (const float*)d_in[7];
    const float* wkm      = (const float*)d_in[8];
    const float* wvm      = (const float*)d_in[9];
    const float* w1       = (const float*)d_in[10];
    const float* w3       = (const float*)d_in[11];
    const float* w2       = (const float*)d_in[12];
    const float* ffn_nw   = (const float*)d_in[13];
    const float* mem_nw   = (const float*)d_in[14];
    const float* omem     = (const float*)d_in[15];
    float* out = (float*)d_out;

    float *p_allout, *p_a, *p_hn, *p_t1, *p_t3, *p_m2, *p_q, *p_k, *p_v;
    cudaGetSymbolAddress((void**)&p_allout, g_allout);
    cudaGetSymbolAddress((void**)&p_a,  g_a);
    cudaGetSymbolAddress((void**)&p_hn, g_hn);
    cudaGetSymbolAddress((void**)&p_t1, g_t1);
    cudaGetSymbolAddress((void**)&p_t3, g_t3);
    cudaGetSymbolAddress((void**)&p_m2, g_m2);
    cudaGetSymbolAddress((void**)&p_q,  g_q);
    cudaGetSymbolAddress((void**)&p_k,  g_k);
    cudaGetSymbolAddress((void**)&p_v,  g_v);

    cudaFuncSetAttribute(attn_kernel,
                         cudaFuncAttributeMaxDynamicSharedMemorySize, ATTN_SMEM);
    cudaFuncSetAttribute(mma_gemm_kernel<false>,
                         cudaFuncAttributeMaxDynamicSharedMemorySize, GEMM_SMEM);
    cudaFuncSetAttribute(mma_gemm_kernel<true>,
                         cudaFuncAttributeMaxDynamicSharedMemorySize, GEMM_SMEM);

    const long long MD  = (long long)M_ * D_;
    const long long LD  = (long long)L_ * D_;
    const long long MH  = (long long)M_ * HID_;
    const long long SD  = (long long)S_ * D_;

    for (int s = 0; s < NSTEP; s++) {
        const float* om = (s == 0) ? omem : (p_allout + (size_t)(s - 1) * M_ * D_);
        const long long omB = (s == 0) ? 0LL : SD;

        // a = om @ wm
        mma_gemm_kernel<false><<<dim3(8, 4, 2), 256, GEMM_SMEM>>>(
            om, omB, wm, wm, wm, p_a, p_a, p_a, MD, MD, MD, D_, D_, 8);
        // hn = rmsnorm(a, ffn_norm_w)
        rmsnorm_kernel<<<B_ * M_, 256>>>(p_a, ffn_nw, p_hn);
        // t1 = hn @ w1 ; t3 = hn @ w3 (fused)
        mma_gemm_kernel<false><<<dim3(44, 4, 2), 256, GEMM_SMEM>>>(
            p_hn, MD, w1, w3, w3, p_t1, p_t3, p_t3, MH, MH, MH, D_, HID_, 22);
        // t1 = silu(t1) * t3
        silu_gate_kernel<<<(B_ * M_ * HID_ + 255) / 256, 256>>>(p_t1, p_t3, B_ * M_ * HID_);
        // a += t1 @ w2
        mma_gemm_kernel<true><<<dim3(8, 4, 2), 256, GEMM_SMEM>>>(
            p_t1, MH, w2, w2, w2, p_a, p_a, p_a, MD, MD, MD, HID_, D_, 8);
        // m2 = rmsnorm(a, mem_norm_w)
        rmsnorm_kernel<<<B_ * M_, 256>>>(p_a, mem_nw, p_m2);
        // mk -> k[:, :512], mv -> v[:, :512] (fused)
        mma_gemm_kernel<false><<<dim3(16, 4, 2), 256, GEMM_SMEM>>>(
            p_m2, MD, wkm, wvm, wvm, p_k, p_v, p_v, LD, LD, LD, D_, D_, 8);
        // xq ; xk -> k[:, 512:] ; xv -> v[:, 512:] (fused)
        const float* xs = x + (size_t)s * M_ * D_;
        mma_gemm_kernel<false><<<dim3(24, 4, 2), 256, GEMM_SMEM>>>(
            xs, SD, wq, wk, wv, p_q, p_k + (size_t)M_ * D_, p_v + (size_t)M_ * D_,
            MD, LD, LD, D_, D_, 8);
        // RoPE
        {
            int nk = B_ * L_ * (D_ / 2);
            rope_kernel<<<(nk + 255) / 256, 256>>>(p_k, cosT, sinT, L_, 0, nk);
            int nq = B_ * M_ * (D_ / 2);
            rope_kernel<<<(nq + 255) / 256, 256>>>(p_q, cosT, sinT, M_, M_, nq);
        }
        // Attention
        attn_kernel<<<dim3(M_ / 64, H_, B_), 256, ATTN_SMEM>>>(p_q, p_k, p_v, p_allout, s * M_);
    }

    // out = allout @ wo
    mma_gemm_kernel<false><<<dim3(8, 64, 1), 256, GEMM_SMEM>>>(
        p_allout, 0LL, wo, wo, wo, out, out, out, 0LL, 0LL, 0LL, D_, D_, 8);
}

// round 9
// speedup vs baseline: 1.1230x; 1.1230x over previous
#include <cuda_runtime.h>
#include <cuda_bf16.h>
#include <cstdint>
#include <math.h>

// Problem constants
#define B_  2
#define S_  4096
#define D_  1024
#define H_  16
#define HD_ 64
#define M_  512
#define L_  1024
#define HID_ 2816
#define NSTEP 8

// ---------------------------------------------------------------------------
// Scratch (device globals; no allocation allowed)
// ---------------------------------------------------------------------------
__device__ float g_allout[B_ * S_ * D_];   // attention outputs, all steps
__device__ float g_qx[B_ * S_ * D_];       // x @ wq, roped (all steps)
__device__ float g_kx[B_ * S_ * D_];       // x @ wk, roped (all steps)
__device__ float g_vx[B_ * S_ * D_];       // x @ wv (all steps)
__device__ float g_a  [B_ * M_ * D_];
__device__ float g_hn [B_ * M_ * D_];
__device__ float g_t1 [B_ * M_ * HID_];
__device__ float g_t3 [B_ * M_ * HID_];
__device__ float g_m2 [B_ * M_ * D_];
__device__ float g_k  [B_ * M_ * D_];      // mem-part K (per step, roped)
__device__ float g_v  [B_ * M_ * D_];      // mem-part V (per step)

// ---------------------------------------------------------------------------
// Warp-level bf16 MMA + ldmatrix helpers (valid under compute_103 target)
// ---------------------------------------------------------------------------
__device__ __forceinline__ void mma16816(float* c,
                                         uint32_t a0, uint32_t a1, uint32_t a2, uint32_t a3,
                                         uint32_t b0, uint32_t b1)
{
    asm volatile(
        "mma.sync.aligned.m16n8k16.row.col.f32.bf16.bf16.f32 "
        "{%0,%1,%2,%3}, {%4,%5,%6,%7}, {%8,%9}, {%0,%1,%2,%3};"
        : "+f"(c[0]), "+f"(c[1]), "+f"(c[2]), "+f"(c[3])
        : "r"(a0), "r"(a1), "r"(a2), "r"(a3), "r"(b0), "r"(b1));
}

__device__ __forceinline__ void ldsm4(uint32_t& r0, uint32_t& r1,
                                      uint32_t& r2, uint32_t& r3, uint32_t addr)
{
    asm volatile("ldmatrix.sync.aligned.m8n8.x4.shared.b16 {%0,%1,%2,%3}, [%4];"
        : "=r"(r0), "=r"(r1), "=r"(r2), "=r"(r3) : "r"(addr));
}

__device__ __forceinline__ uint32_t smem_u32(const void* p) {
    uint32_t a;
    asm("{ .reg .u64 t; cvta.to.shared.u64 t, %1; cvt.u32.u64 %0, t; }"
        : "=r"(a) : "l"(p));
    return a;
}

// ---------------------------------------------------------------------------
// Split-bf16 GEMM on tensor cores (acc = Ah*Bh + Ah*Bl + Al*Bh).
// Tile 128x128, BK=32, 256 threads (2M x 4N warps, warp tile 64x32).
// grid: (nmat * tilesN, rows/128, batch).
// ---------------------------------------------------------------------------
#define BK 32
#define AST 40                      // bf16 row stride
#define ASTB (AST * 2)              // bytes
#define A_HALF (128 * AST * 2)      // 10240 bytes per half
#define GEMM_SMEM (4 * A_HALF)      // 40960 bytes

template <bool ACC>
__global__ __launch_bounds__(256, 2)
void mma_gemm_kernel(const float* __restrict__ A, long long aBatch,
                     const float* __restrict__ B0, const float* __restrict__ B1,
                     const float* __restrict__ B2,
                     float* __restrict__ C0, float* __restrict__ C1, float* __restrict__ C2,
                     long long cB0, long long cB1, long long cB2,
                     int K, int N, int tilesN)
{
    extern __shared__ char smem[];
    __nv_bfloat16* Ahi = (__nv_bfloat16*)smem;
    __nv_bfloat16* Alo = (__nv_bfloat16*)(smem + A_HALF);
    __nv_bfloat16* Bhi = (__nv_bfloat16*)(smem + 2 * A_HALF);
    __nv_bfloat16* Blo = (__nv_bfloat16*)(smem + 3 * A_HALF);

    const int tid = threadIdx.x;
    const int wid = tid >> 5, lane = tid & 31;
    const int wm = wid & 1, wn = wid >> 1;
    const int r  = lane >> 2, qc = (lane & 3) * 2;

    const int tn  = blockIdx.x % tilesN;
    const int mat = blockIdx.x / tilesN;
    const int bz  = blockIdx.z;
    const int m0  = blockIdx.y * 128;
    const int n0  = tn * 128;

    const float* Bm = (mat == 0) ? B0 : ((mat == 1) ? B1 : B2);
    float*       Cm = (mat == 0) ? C0 : ((mat == 1) ? C1 : C2);
    const long long cB = (mat == 0) ? cB0 : ((mat == 1) ? cB1 : cB2);

    const float* Ab = A + (long long)bz * aBatch + (long long)m0 * K;

    // ldmatrix per-lane byte offsets
    const uint32_t sAhi = smem_u32(Ahi);
    const uint32_t sBhi = smem_u32(Bhi);
    const uint32_t aLaneOff = (uint32_t)((lane & 15) * AST + (lane >> 4) * 8) * 2;
    const uint32_t bLaneOff = (uint32_t)((((lane & 7) + ((lane >> 4) << 3)) * AST
                                          + ((lane >> 3) & 1) * 8) * 2);

    // Load thread mappings
    const int ar  = tid >> 1,  akb = (tid & 1) * 16;   // A: 128 rows x 32 k
    const int bn  = tid & 127, bkb = (tid >> 7) * 16;  // B: col per thread, 16 k

    float4 pa[4];
    float  pb[16];
    {
        const float* Ap = Ab + (size_t)ar * K + akb;
        #pragma unroll
        for (int j = 0; j < 4; j++) pa[j] = *(const float4*)(Ap + j * 4);
        const float* Bp = Bm + (size_t)bkb * N + n0 + bn;
        #pragma unroll
        for (int j = 0; j < 16; j++) pb[j] = Bp[(size_t)j * N];
    }

    float acc[4][4][4];
    #pragma unroll
    for (int i = 0; i < 4; i++)
        #pragma unroll
        for (int j = 0; j < 4; j++)
            #pragma unroll
            for (int e = 0; e < 4; e++) acc[i][j][e] = 0.f;

    const int NC = K / BK;
    #pragma unroll 1
    for (int kc = 0; kc < NC; kc++) {
        // ---- convert + store current chunk to smem ----
        #pragma unroll
        for (int j = 0; j < 4; j++) {
            float4 v = pa[j];
            __nv_bfloat16 h0 = __float2bfloat16(v.x);
            __nv_bfloat16 h1 = __float2bfloat16(v.y);
            __nv_bfloat16 h2 = __float2bfloat16(v.z);
            __nv_bfloat16 h3 = __float2bfloat16(v.w);
            __nv_bfloat162 hp0 = __halves2bfloat162(h0, h1);
            __nv_bfloat162 hp1 = __halves2bfloat162(h2, h3);
            __nv_bfloat162 lp0 = __floats2bfloat162_rn(v.x - __bfloat162float(h0),
                                                       v.y - __bfloat162float(h1));
            __nv_bfloat162 lp1 = __floats2bfloat162_rn(v.z - __bfloat162float(h2),
                                                       v.w - __bfloat162float(h3));
            int off = ar * AST + akb + j * 4;
            *(uint2*)&Ahi[off] = make_uint2(*(uint32_t*)&hp0, *(uint32_t*)&hp1);
            *(uint2*)&Alo[off] = make_uint2(*(uint32_t*)&lp0, *(uint32_t*)&lp1);
        }
        #pragma unroll
        for (int g = 0; g < 4; g++) {
            __nv_bfloat16 h0 = __float2bfloat16(pb[g * 4 + 0]);
            __nv_bfloat16 h1 = __float2bfloat16(pb[g * 4 + 1]);
            __nv_bfloat16 h2 = __float2bfloat16(pb[g * 4 + 2]);
            __nv_bfloat16 h3 = __float2bfloat16(pb[g * 4 + 3]);
            __nv_bfloat162 hp0 = __halves2bfloat162(h0, h1);
            __nv_bfloat162 hp1 = __halves2bfloat162(h2, h3);
            __nv_bfloat162 lp0 = __floats2bfloat162_rn(pb[g*4+0] - __bfloat162float(h0),
                                                       pb[g*4+1] - __bfloat162float(h1));
            __nv_bfloat162 lp1 = __floats2bfloat162_rn(pb[g*4+2] - __bfloat162float(h2),
                                                       pb[g*4+3] - __bfloat162float(h3));
            int off = bn * AST + bkb + g * 4;
            *(uint2*)&Bhi[off] = make_uint2(*(uint32_t*)&hp0, *(uint32_t*)&hp1);
            *(uint2*)&Blo[off] = make_uint2(*(uint32_t*)&lp0, *(uint32_t*)&lp1);
        }
        __syncthreads();

        // ---- prefetch next chunk ----
        if (kc + 1 < NC) {
            const int k0n = (kc + 1) * BK;
            const float* Ap = Ab + (size_t)ar * K + k0n + akb;
            #pragma unroll
            for (int j = 0; j < 4; j++) pa[j] = *(const float4*)(Ap + j * 4);
            const float* Bp = Bm + (size_t)(k0n + bkb) * N + n0 + bn;
            #pragma unroll
            for (int j = 0; j < 16; j++) pb[j] = Bp[(size_t)j * N];
        }

        // ---- MMA: 2 k-steps of 16, fragments via ldmatrix ----
        #pragma unroll
        for (int ks = 0; ks < 2; ks++) {
            const uint32_t kOff = ks * 32;     // 16 bf16 = 32 bytes
            uint32_t bh[2][4], bl[2][4];
            #pragma unroll
            for (int p = 0; p < 2; p++) {
                uint32_t baddr = sBhi + (uint32_t)(wn * 32 + p * 16) * ASTB + kOff + bLaneOff;
                ldsm4(bh[p][0], bh[p][1], bh[p][2], bh[p][3], baddr);
                ldsm4(bl[p][0], bl[p][1], bl[p][2], bl[p][3], baddr + A_HALF);
            }
            #pragma unroll
            for (int mt = 0; mt < 4; mt++) {
                uint32_t aaddr = sAhi + (uint32_t)(wm * 64 + mt * 16) * ASTB + kOff + aLaneOff;
                uint32_t ah0, ah1, ah2, ah3, al0, al1, al2, al3;
                ldsm4(ah0, ah1, ah2, ah3, aaddr);
                ldsm4(al0, al1, al2, al3, aaddr + A_HALF);
                #pragma unroll
                for (int nt = 0; nt < 4; nt++) {
                    uint32_t b0 = bh[nt >> 1][(nt & 1) * 2];
                    uint32_t b1 = bh[nt >> 1][(nt & 1) * 2 + 1];
                    uint32_t c0 = bl[nt >> 1][(nt & 1) * 2];
                    uint32_t c1 = bl[nt >> 1][(nt & 1) * 2 + 1];
                    mma16816(acc[mt][nt], ah0, ah1, ah2, ah3, b0, b1);
                    mma16816(acc[mt][nt], ah0, ah1, ah2, ah3, c0, c1);
                    mma16816(acc[mt][nt], al0, al1, al2, al3, b0, b1);
                }
            }
        }
        __syncthreads();
    }

    // ---- epilogue ----
    float* Cb = Cm + (long long)bz * cB;
    #pragma unroll
    for (int mt = 0; mt < 4; mt++) {
        int row0 = m0 + wm * 64 + mt * 16 + r;
        #pragma unroll
        for (int nt = 0; nt < 4; nt++) {
            int col = n0 + wn * 32 + nt * 8 + qc;
            float* p0 = Cb + (size_t)row0 * N + col;
            float* p1 = Cb + (size_t)(row0 + 8) * N + col;
            float2 v0 = make_float2(acc[mt][nt][0], acc[mt][nt][1]);
            float2 v1 = make_float2(acc[mt][nt][2], acc[mt][nt][3]);
            if (ACC) {
                float2 o0 = *(const float2*)p0;
                float2 o1 = *(const float2*)p1;
                v0.x += o0.x; v0.y += o0.y;
                v1.x += o1.x; v1.y += o1.y;
            }
            *(float2*)p0 = v0;
            *(float2*)p1 = v1;
        }
    }
}

// ---------------------------------------------------------------------------
// RMSNorm
// ---------------------------------------------------------------------------
__global__ __launch_bounds__(256)
void rmsnorm_kernel(const float* __restrict__ x, const float* __restrict__ w,
                    float* __restrict__ o)
{
    const int row = blockIdx.x;
    const int tid = threadIdx.x;
    const float4 v = *(const float4*)(x + (size_t)row * D_ + tid * 4);
    float ss = v.x * v.x + v.y * v.y + v.z * v.z + v.w * v.w;
    #pragma unroll
    for (int off = 16; off; off >>= 1)
        ss += __shfl_xor_sync(0xffffffffu, ss, off);
    __shared__ float ws[8];
    __shared__ float s_inv;
    if ((tid & 31) == 0) ws[tid >> 5] = ss;
    __syncthreads();
    if (tid == 0) {
        float t = 0.f;
        #pragma unroll
        for (int i = 0; i < 8; i++) t += ws[i];
        s_inv = rsqrtf(t * (1.0f / D_) + 1e-5f);
    }
    __syncthreads();
    const float inv = s_inv;
    const float4 wv = *(const float4*)(w + tid * 4);
    float4 ov;
    ov.x = v.x * inv * wv.x;
    ov.y = v.y * inv * wv.y;
    ov.z = v.z * inv * wv.z;
    ov.w = v.w * inv * wv.w;
    *(float4*)(o + (size_t)row * D_ + tid * 4) = ov;
}

// ---------------------------------------------------------------------------
// SwiGLU gate (float4)
// ---------------------------------------------------------------------------
__global__ void silu_gate_kernel(float4* __restrict__ t1,
                                 const float4* __restrict__ t3, int n4)
{
    int i = blockIdx.x * blockDim.x + threadIdx.x;
    if (i < n4) {
        float4 a = t1[i];
        float4 b = t3[i];
        float4 o;
        o.x = (a.x / (1.f + __expf(-a.x))) * b.x;
        o.y = (a.y / (1.f + __expf(-a.y))) * b.y;
        o.z = (a.z / (1.f + __expf(-a.z))) * b.z;
        o.w = (a.w / (1.f + __expf(-a.w))) * b.w;
        t1[i] = o;
    }
}

// ---------------------------------------------------------------------------
// RoPE: rows of width 1024; position = posOff + (row % rowsMod)
// ---------------------------------------------------------------------------
__global__ void rope_kernel(float* __restrict__ t,
                            const float* __restrict__ cosT,
                            const float* __restrict__ sinT,
                            int rowsMod, int posOff, int nPairs)
{
    int id = blockIdx.x * blockDim.x + threadIdx.x;
    if (id >= nPairs) return;
    int pair = id & 511;
    int row  = id >> 9;
    int pos  = posOff + (row % rowsMod);
    int i    = pair & 31;
    float c = cosT[pos * 32 + i];
    float s = sinT[pos * 32 + i];
    float2* p = (float2*)(t + (size_t)row * D_ + pair * 2);
    float2 v = *p;
    float2 o;
    o.x = v.x * c - v.y * s;
    o.y = v.x * s + v.y * c;
    *p = o;
}

// ---------------------------------------------------------------------------
// Flash-style causal attention (x-part queries only).
// K/V come from two sources: mem part (per-step buffers, kt<8) and
// precomputed x part (big (B,S,D) buffers at step offset sBase, kt>=8).
// ---------------------------------------------------------------------------
#define ALD 65
#define ATTN_SMEM ((4 * 64 * ALD + 3 * 64) * (int)sizeof(float))

__global__ __launch_bounds__(256)
void attn_kernel(const float* __restrict__ Qx,
                 const float* __restrict__ Km, const float* __restrict__ Vm,
                 const float* __restrict__ Kx, const float* __restrict__ Vx,
                 float* __restrict__ Out, int sBase)
{
    extern __shared__ float sm[];
    float* Qs   = sm;
    float* Ks   = Qs + 64 * ALD;
    float* Vs   = Ks + 64 * ALD;
    float* Ss   = Vs + 64 * ALD;
    float* mrow = Ss + 64 * ALD;
    float* lrow = mrow + 64;
    float* crow = lrow + 64;

    const int b  = blockIdx.z;
    const int h  = blockIdx.y;
    const int qt = blockIdx.x;
    const int tid = threadIdx.x;
    const int tx = tid & 15, ty = tid >> 4;
    const int q0 = qt * 64;
    const float scale = 0.125f;

    for (int e = tid; e < 64 * 16; e += 256) {
        int i = e >> 4, d4 = (e & 15) * 4;
        float4 v = *(const float4*)&Qx[((size_t)(b * S_ + sBase + q0 + i)) * D_ + h * HD_ + d4];
        Qs[i * ALD + d4 + 0] = v.x;
        Qs[i * ALD + d4 + 1] = v.y;
        Qs[i * ALD + d4 + 2] = v.z;
        Qs[i * ALD + d4 + 3] = v.w;
    }
    if (tid < 64) { mrow[tid] = -1e30f; lrow[tid] = 0.f; }
    float acc[4][4];
    #pragma unroll
    for (int i = 0; i < 4; i++)
        #pragma unroll
        for (int j = 0; j < 4; j++) acc[i][j] = 0.f;
    __syncthreads();

    const int nkt = qt + 9;
    for (int kt = 0; kt < nkt; kt++) {
        const float* Kp;
        const float* Vp;
        size_t rb;
        if (kt < 8) {
            Kp = Km; Vp = Vm;
            rb = (size_t)(b * M_ + kt * 64);
        } else {
            Kp = Kx; Vp = Vx;
            rb = (size_t)(b * S_ + sBase + (kt - 8) * 64);
        }
        for (int e = tid; e < 64 * 16; e += 256) {
            int j = e >> 4, d4 = (e & 15) * 4;
            size_t base = (rb + j) * D_ + h * HD_ + d4;
            float4 kv = *(const float4*)&Kp[base];
            Ks[j * ALD + d4 + 0] = kv.x;
            Ks[j * ALD + d4 + 1] = kv.y;
            Ks[j * ALD + d4 + 2] = kv.z;
            Ks[j * ALD + d4 + 3] = kv.w;
            float4 vv = *(const float4*)&Vp[base];
            Vs[j * ALD + d4 + 0] = vv.x;
            Vs[j * ALD + d4 + 1] = vv.y;
            Vs[j * ALD + d4 + 2] = vv.z;
            Vs[j * ALD + d4 + 3] = vv.w;
        }
        __syncthreads();

        float s4[4][4];
        #pragma unroll
        for (int i = 0; i < 4; i++)
            #pragma unroll
            for (int j = 0; j < 4; j++) s4[i][j] = 0.f;
        for (int d = 0; d < 64; d++) {
            float rq[4], rk[4];
            #pragma unroll
            for (int ii = 0; ii < 4; ii++) rq[ii] = Qs[(ty * 4 + ii) * ALD + d];
            #pragma unroll
            for (int jj = 0; jj < 4; jj++) rk[jj] = Ks[(tx * 4 + jj) * ALD + d];
            #pragma unroll
            for (int ii = 0; ii < 4; ii++)
                #pragma unroll
                for (int jj = 0; jj < 4; jj++)
                    s4[ii][jj] = fmaf(rq[ii], rk[jj], s4[ii][jj]);
        }
        const int qg0 = M_ + q0;
        #pragma unroll
        for (int ii = 0; ii < 4; ii++) {
            int qi = qg0 + ty * 4 + ii;
            #pragma unroll
            for (int jj = 0; jj < 4; jj++) {
                int kj = kt * 64 + tx * 4 + jj;
                float val = (kj <= qi) ? s4[ii][jj] * scale : -1e30f;
                Ss[(ty * 4 + ii) * ALD + tx * 4 + jj] = val;
            }
        }
        __syncthreads();

        if (tid < 64) {
            float mold = mrow[tid];
            float mx = mold;
            for (int j = 0; j < 64; j++) mx = fmaxf(mx, Ss[tid * ALD + j]);
            float c = __expf(mold - mx);
            float sum = 0.f;
            for (int j = 0; j < 64; j++) {
                float p = __expf(Ss[tid * ALD + j] - mx);
                Ss[tid * ALD + j] = p;
                sum += p;
            }
            mrow[tid] = mx;
            lrow[tid] = lrow[tid] * c + sum;
            crow[tid] = c;
        }
        __syncthreads();

        float cc[4];
        #pragma unroll
        for (int ii = 0; ii < 4; ii++) cc[ii] = crow[ty * 4 + ii];
        #pragma unroll
        for (int ii = 0; ii < 4; ii++)
            #pragma unroll
            for (int dd = 0; dd < 4; dd++) acc[ii][dd] *= cc[ii];
        for (int j = 0; j < 64; j++) {
            float rp[4], rv[4];
            #pragma unroll
            for (int ii = 0; ii < 4; ii++) rp[ii] = Ss[(ty * 4 + ii) * ALD + j];
            #pragma unroll
            for (int dd = 0; dd < 4; dd++) rv[dd] = Vs[j * ALD + tx * 4 + dd];
            #pragma unroll
            for (int ii = 0; ii < 4; ii++)
                #pragma unroll
                for (int dd = 0; dd < 4; dd++)
                    acc[ii][dd] = fmaf(rp[ii], rv[dd], acc[ii][dd]);
        }
        __syncthreads();
    }

    if (tid < 64) crow[tid] = 1.f / lrow[tid];
    __syncthreads();
    #pragma unroll
    for (int ii = 0; ii < 4; ii++) {
        float inv = crow[ty * 4 + ii];
        int grow = b * S_ + sBase + q0 + ty * 4 + ii;
        float4 o;
        o.x = acc[ii][0] * inv;
        o.y = acc[ii][1] * inv;
        o.z = acc[ii][2] * inv;
        o.w = acc[ii][3] * inv;
        *(float4*)&Out[(size_t)grow * D_ + h * HD_ + tx * 4] = o;
    }
}

// ---------------------------------------------------------------------------
// Launch
// ---------------------------------------------------------------------------
extern "C" void kernel_launch(void* const* d_in, const int* in_sizes, int n_in,
                              void* d_out, int out_size)
{
    const float* x        = (const float*)d_in[0];
    const float* cosT     = (const float*)d_in[1];
    const float* sinT     = (const float*)d_in[2];
    const float* wq       = (const float*)d_in[3];
    const float* wk       = (const float*)d_in[4];
    const float* wv       = (const float*)d_in[5];
    const float* wo       = (const float*)d_in[6];
    const float* wm       = (const float*)d_in[7];
    const float* wkm      = (const float*)d_in[8];
    const float* wvm      = (const float*)d_in[9];
    const float* w1       = (const float*)d_in[10];
    const float* w3       = (const float*)d_in[11];
    const float* w2       = (const float*)d_in[12];
    const float* ffn_nw   = (const float*)d_in[13];
    const float* mem_nw   = (const float*)d_in[14];
    const float* omem     = (const float*)d_in[15];
    float* out = (float*)d_out;

    float *p_allout, *p_qx, *p_kx, *p_vx, *p_a, *p_hn, *p_t1, *p_t3, *p_m2, *p_k, *p_v;
    cudaGetSymbolAddress((void**)&p_allout, g_allout);
    cudaGetSymbolAddress((void**)&p_qx, g_qx);
    cudaGetSymbolAddress((void**)&p_kx, g_kx);
    cudaGetSymbolAddress((void**)&p_vx, g_vx);
    cudaGetSymbolAddress((void**)&p_a,  g_a);
    cudaGetSymbolAddress((void**)&p_hn, g_hn);
    cudaGetSymbolAddress((void**)&p_t1, g_t1);
    cudaGetSymbolAddress((void**)&p_t3, g_t3);
    cudaGetSymbolAddress((void**)&p_m2, g_m2);
    cudaGetSymbolAddress((void**)&p_k,  g_k);
    cudaGetSymbolAddress((void**)&p_v,  g_v);

    cudaFuncSetAttribute(attn_kernel,
                         cudaFuncAttributeMaxDynamicSharedMemorySize, ATTN_SMEM);
    cudaFuncSetAttribute(mma_gemm_kernel<false>,
                         cudaFuncAttributeMaxDynamicSharedMemorySize, GEMM_SMEM);
    cudaFuncSetAttribute(mma_gemm_kernel<true>,
                         cudaFuncAttributeMaxDynamicSharedMemorySize, GEMM_SMEM);

    const long long MD  = (long long)M_ * D_;
    const long long MH  = (long long)M_ * HID_;
    const long long SD  = (long long)S_ * D_;

    // ---- Upfront: all-step QKV projections + RoPE (independent of chain) ----
    mma_gemm_kernel<false><<<dim3(24, 32, 2), 256, GEMM_SMEM>>>(
        x, SD, wq, wk, wv, p_qx, p_kx, p_vx, SD, SD, SD, D_, D_, 8);
    {
        int n = B_ * S_ * (D_ / 2);
        rope_kernel<<<(n + 255) / 256, 256>>>(p_qx, cosT, sinT, 512, M_, n);
        rope_kernel<<<(n + 255) / 256, 256>>>(p_kx, cosT, sinT, 512, M_, n);
    }

    // ---- Sequential memory chain ----
    for (int s = 0; s < NSTEP; s++) {
        const float* om = (s == 0) ? omem : (p_allout + (size_t)(s - 1) * M_ * D_);
        const long long omB = (s == 0) ? 0LL : SD;

        // a = om @ wm
        mma_gemm_kernel<false><<<dim3(8, 4, 2), 256, GEMM_SMEM>>>(
            om, omB, wm, wm, wm, p_a, p_a, p_a, MD, MD, MD, D_, D_, 8);
        // hn = rmsnorm(a, ffn_norm_w)
        rmsnorm_kernel<<<B_ * M_, 256>>>(p_a, ffn_nw, p_hn);
        // t1 = hn @ w1 ; t3 = hn @ w3 (fused)
        mma_gemm_kernel<false><<<dim3(44, 4, 2), 256, GEMM_SMEM>>>(
            p_hn, MD, w1, w3, w3, p_t1, p_t3, p_t3, MH, MH, MH, D_, HID_, 22);
        // t1 = silu(t1) * t3
        silu_gate_kernel<<<(B_ * M_ * HID_ / 4 + 255) / 256, 256>>>(
            (float4*)p_t1, (const float4*)p_t3, B_ * M_ * HID_ / 4);
        // a += t1 @ w2
        mma_gemm_kernel<true><<<dim3(8, 4, 2), 256, GEMM_SMEM>>>(
            p_t1, MH, w2, w2, w2, p_a, p_a, p_a, MD, MD, MD, HID_, D_, 8);
        // m2 = rmsnorm(a, mem_norm_w)
        rmsnorm_kernel<<<B_ * M_, 256>>>(p_a, mem_nw, p_m2);
        // mk, mv (fused)
        mma_gemm_kernel<false><<<dim3(16, 4, 2), 256, GEMM_SMEM>>>(
            p_m2, MD, wkm, wvm, wvm, p_k, p_v, p_v, MD, MD, MD, D_, D_, 8);
        // RoPE on mk (positions 0..511)
        {
            int n = B_ * M_ * (D_ / 2);
            rope_kernel<<<(n + 255) / 256, 256>>>(p_k, cosT, sinT, 512, 0, n);
        }
        // Attention
        attn_kernel<<<dim3(M_ / 64, H_, B_), 256, ATTN_SMEM>>>(
            p_qx, p_k, p_v, p_kx, p_vx, p_allout, s * M_);
    }

    // out = allout @ wo
    mma_gemm_kernel<false><<<dim3(8, 64, 1), 256, GEMM_SMEM>>>(
        p_allout, 0LL, wo, wo, wo, out, out, out, 0LL, 0LL, 0LL, D_, D_, 8);
}

// round 11
// speedup vs baseline: 1.4493x; 1.2906x over previous
#include <cuda_runtime.h>
#include <cuda_bf16.h>
#include <cstdint>
#include <math.h>

// Problem constants
#define B_  2
#define S_  4096
#define D_  1024
#define H_  16
#define HD_ 64
#define M_  512
#define L_  1024
#define HID_ 2816
#define NSTEP 8

// ---------------------------------------------------------------------------
// Scratch (device globals; no allocation allowed)
// ---------------------------------------------------------------------------
__device__ float g_allout[B_ * S_ * D_];   // attention outputs, all steps
__device__ float g_qx[B_ * S_ * D_];       // x @ wq, roped (all steps)
__device__ float g_kx[B_ * S_ * D_];       // x @ wk, roped (all steps)
__device__ float g_vx[B_ * S_ * D_];       // x @ wv (all steps)
__device__ float g_a  [B_ * M_ * D_];
__device__ float g_hn [B_ * M_ * D_];
__device__ float g_t1 [B_ * M_ * HID_];
__device__ float g_t3 [B_ * M_ * HID_];
__device__ float g_m2 [B_ * M_ * D_];
__device__ float g_k  [B_ * M_ * D_];      // mem-part K (per step, roped)
__device__ float g_v  [B_ * M_ * D_];      // mem-part V (per step)

// ---------------------------------------------------------------------------
// Warp-level bf16 MMA + ldmatrix helpers (valid under compute_103 target)
// ---------------------------------------------------------------------------
__device__ __forceinline__ void mma16816(float* c,
                                         uint32_t a0, uint32_t a1, uint32_t a2, uint32_t a3,
                                         uint32_t b0, uint32_t b1)
{
    asm volatile(
        "mma.sync.aligned.m16n8k16.row.col.f32.bf16.bf16.f32 "
        "{%0,%1,%2,%3}, {%4,%5,%6,%7}, {%8,%9}, {%0,%1,%2,%3};"
        : "+f"(c[0]), "+f"(c[1]), "+f"(c[2]), "+f"(c[3])
        : "r"(a0), "r"(a1), "r"(a2), "r"(a3), "r"(b0), "r"(b1));
}

__device__ __forceinline__ void ldsm4(uint32_t& r0, uint32_t& r1,
                                      uint32_t& r2, uint32_t& r3, uint32_t addr)
{
    asm volatile("ldmatrix.sync.aligned.m8n8.x4.shared.b16 {%0,%1,%2,%3}, [%4];"
        : "=r"(r0), "=r"(r1), "=r"(r2), "=r"(r3) : "r"(addr));
}

__device__ __forceinline__ uint32_t smem_u32(const void* p) {
    uint32_t a;
    asm("{ .reg .u64 t; cvta.to.shared.u64 t, %1; cvt.u32.u64 %0, t; }"
        : "=r"(a) : "l"(p));
    return a;
}

// ---------------------------------------------------------------------------
// Split-bf16 GEMM on tensor cores (acc = Ah*Bh + Ah*Bl + Al*Bh).
// Tile TM x TN (templated), BK=32, 256 threads, 8 warps as 2M x 4N.
// grid: (nmat * tilesN, rows/TM, batch).
// ---------------------------------------------------------------------------
#define BK 32
#define AST 40
#define ASTB (AST * 2)

template <int TM, int TN, bool ACC>
__global__ __launch_bounds__(256, 2)
void mma_gemm_kernel(const float* __restrict__ A, long long aBatch,
                     const float* __restrict__ B0, const float* __restrict__ B1,
                     const float* __restrict__ B2,
                     float* __restrict__ C0, float* __restrict__ C1, float* __restrict__ C2,
                     long long cB0, long long cB1, long long cB2,
                     int K, int N, int tilesN)
{
    constexpr int WM = TM / 2;          // warp rows
    constexpr int WN = TN / 4;          // warp cols
    constexpr int MT = WM / 16;         // 16-row m-tiles per warp
    constexpr int NT = WN / 8;          // 8-col n-tiles per warp
    constexpr int P  = NT / 2;          // ldmatrix x4 pairs for B
    constexpr int A_HALF = TM * AST * 2;
    constexpr int B_HALF = TN * AST * 2;
    constexpr int CA = TM / 32;         // A float4 loads per thread
    constexpr int TPR = 256 / TM;       // threads per A row
    constexpr int NB = TN / 8;          // B scalar loads per thread

    extern __shared__ char smem[];
    __nv_bfloat16* Ahi = (__nv_bfloat16*)smem;
    __nv_bfloat16* Alo = (__nv_bfloat16*)(smem + A_HALF);
    __nv_bfloat16* Bhi = (__nv_bfloat16*)(smem + 2 * A_HALF);
    __nv_bfloat16* Blo = (__nv_bfloat16*)(smem + 2 * A_HALF + B_HALF);

    const int tid = threadIdx.x;
    const int wid = tid >> 5, lane = tid & 31;
    const int wm = wid & 1, wn = wid >> 1;
    const int r  = lane >> 2, qc = (lane & 3) * 2;

    const int tn  = blockIdx.x % tilesN;
    const int mat = blockIdx.x / tilesN;
    const int bz  = blockIdx.z;
    const int m0  = blockIdx.y * TM;
    const int n0  = tn * TN;

    const float* Bm = (mat == 0) ? B0 : ((mat == 1) ? B1 : B2);
    float*       Cm = (mat == 0) ? C0 : ((mat == 1) ? C1 : C2);
    const long long cB = (mat == 0) ? cB0 : ((mat == 1) ? cB1 : cB2);

    const float* Ab = A + (long long)bz * aBatch + (long long)m0 * K;

    const uint32_t sAhi = smem_u32(Ahi);
    const uint32_t sBhi = smem_u32(Bhi);
    const uint32_t aLaneOff = (uint32_t)((lane & 15) * AST + (lane >> 4) * 8) * 2;
    const uint32_t bLaneOff = (uint32_t)((((lane & 7) + ((lane >> 4) << 3)) * AST
                                          + ((lane >> 3) & 1) * 8) * 2);

    const int ar  = tid / TPR, akb = (tid % TPR) * (32 / TPR);
    const int bn  = tid % TN,  bkb = (tid / TN) * (TN / 8);

    float4 pa[CA];
    float  pb[NB];
    {
        const float* Ap = Ab + (size_t)ar * K + akb;
        #pragma unroll
        for (int j = 0; j < CA; j++) pa[j] = *(const float4*)(Ap + j * 4);
        const float* Bp = Bm + (size_t)bkb * N + n0 + bn;
        #pragma unroll
        for (int j = 0; j < NB; j++) pb[j] = Bp[(size_t)j * N];
    }

    float acc[MT][NT][4];
    #pragma unroll
    for (int i = 0; i < MT; i++)
        #pragma unroll
        for (int j = 0; j < NT; j++)
            #pragma unroll
            for (int e = 0; e < 4; e++) acc[i][j][e] = 0.f;

    const int NC = K / BK;
    #pragma unroll 1
    for (int kc = 0; kc < NC; kc++) {
        // ---- convert + store current chunk to smem ----
        #pragma unroll
        for (int j = 0; j < CA; j++) {
            float4 v = pa[j];
            __nv_bfloat16 h0 = __float2bfloat16(v.x);
            __nv_bfloat16 h1 = __float2bfloat16(v.y);
            __nv_bfloat16 h2 = __float2bfloat16(v.z);
            __nv_bfloat16 h3 = __float2bfloat16(v.w);
            __nv_bfloat162 hp0 = __halves2bfloat162(h0, h1);
            __nv_bfloat162 hp1 = __halves2bfloat162(h2, h3);
            __nv_bfloat162 lp0 = __floats2bfloat162_rn(v.x - __bfloat162float(h0),
                                                       v.y - __bfloat162float(h1));
            __nv_bfloat162 lp1 = __floats2bfloat162_rn(v.z - __bfloat162float(h2),
                                                       v.w - __bfloat162float(h3));
            int off = ar * AST + akb + j * 4;
            *(uint2*)&Ahi[off] = make_uint2(*(uint32_t*)&hp0, *(uint32_t*)&hp1);
            *(uint2*)&Alo[off] = make_uint2(*(uint32_t*)&lp0, *(uint32_t*)&lp1);
        }
        #pragma unroll
        for (int g = 0; g < NB / 4; g++) {
            __nv_bfloat16 h0 = __float2bfloat16(pb[g * 4 + 0]);
            __nv_bfloat16 h1 = __float2bfloat16(pb[g * 4 + 1]);
            __nv_bfloat16 h2 = __float2bfloat16(pb[g * 4 + 2]);
            __nv_bfloat16 h3 = __float2bfloat16(pb[g * 4 + 3]);
            __nv_bfloat162 hp0 = __halves2bfloat162(h0, h1);
            __nv_bfloat162 hp1 = __halves2bfloat162(h2, h3);
            __nv_bfloat162 lp0 = __floats2bfloat162_rn(pb[g*4+0] - __bfloat162float(h0),
                                                       pb[g*4+1] - __bfloat162float(h1));
            __nv_bfloat162 lp1 = __floats2bfloat162_rn(pb[g*4+2] - __bfloat162float(h2),
                                                       pb[g*4+3] - __bfloat162float(h3));
            int off = bn * AST + bkb + g * 4;
            *(uint2*)&Bhi[off] = make_uint2(*(uint32_t*)&hp0, *(uint32_t*)&hp1);
            *(uint2*)&Blo[off] = make_uint2(*(uint32_t*)&lp0, *(uint32_t*)&lp1);
        }
        __syncthreads();

        // ---- prefetch next chunk ----
        if (kc + 1 < NC) {
            const int k0n = (kc + 1) * BK;
            const float* Ap = Ab + (size_t)ar * K + k0n + akb;
            #pragma unroll
            for (int j = 0; j < CA; j++) pa[j] = *(const float4*)(Ap + j * 4);
            const float* Bp = Bm + (size_t)(k0n + bkb) * N + n0 + bn;
            #pragma unroll
            for (int j = 0; j < NB; j++) pb[j] = Bp[(size_t)j * N];
        }

        // ---- MMA: 2 k-steps of 16, fragments via ldmatrix ----
        #pragma unroll
        for (int ks = 0; ks < 2; ks++) {
            const uint32_t kOff = ks * 32;
            uint32_t bh[P][4], bl[P][4];
            #pragma unroll
            for (int p = 0; p < P; p++) {
                uint32_t baddr = sBhi + (uint32_t)(wn * WN + p * 16) * ASTB + kOff + bLaneOff;
                ldsm4(bh[p][0], bh[p][1], bh[p][2], bh[p][3], baddr);
                ldsm4(bl[p][0], bl[p][1], bl[p][2], bl[p][3], baddr + B_HALF);
            }
            #pragma unroll
            for (int mt = 0; mt < MT; mt++) {
                uint32_t aaddr = sAhi + (uint32_t)(wm * WM + mt * 16) * ASTB + kOff + aLaneOff;
                uint32_t ah0, ah1, ah2, ah3, al0, al1, al2, al3;
                ldsm4(ah0, ah1, ah2, ah3, aaddr);
                ldsm4(al0, al1, al2, al3, aaddr + A_HALF);
                #pragma unroll
                for (int nt = 0; nt < NT; nt++) {
                    uint32_t b0 = bh[nt >> 1][(nt & 1) * 2];
                    uint32_t b1 = bh[nt >> 1][(nt & 1) * 2 + 1];
                    uint32_t c0 = bl[nt >> 1][(nt & 1) * 2];
                    uint32_t c1 = bl[nt >> 1][(nt & 1) * 2 + 1];
                    mma16816(acc[mt][nt], ah0, ah1, ah2, ah3, b0, b1);
                    mma16816(acc[mt][nt], ah0, ah1, ah2, ah3, c0, c1);
                    mma16816(acc[mt][nt], al0, al1, al2, al3, b0, b1);
                }
            }
        }
        __syncthreads();
    }

    // ---- epilogue ----
    float* Cb = Cm + (long long)bz * cB;
    #pragma unroll
    for (int mt = 0; mt < MT; mt++) {
        int row0 = m0 + wm * WM + mt * 16 + r;
        #pragma unroll
        for (int nt = 0; nt < NT; nt++) {
            int col = n0 + wn * WN + nt * 8 + qc;
            float* p0 = Cb + (size_t)row0 * N + col;
            float* p1 = Cb + (size_t)(row0 + 8) * N + col;
            float2 v0 = make_float2(acc[mt][nt][0], acc[mt][nt][1]);
            float2 v1 = make_float2(acc[mt][nt][2], acc[mt][nt][3]);
            if (ACC) {
                float2 o0 = *(const float2*)p0;
                float2 o1 = *(const float2*)p1;
                v0.x += o0.x; v0.y += o0.y;
                v1.x += o1.x; v1.y += o1.y;
            }
            *(float2*)p0 = v0;
            *(float2*)p1 = v1;
        }
    }
}

// SMEM sizes per instantiation
#define SMEM_OF(TM, TN) (2 * (TM) * AST * 2 + 2 * (TN) * AST * 2)

// ---------------------------------------------------------------------------
// RMSNorm
// ---------------------------------------------------------------------------
__global__ __launch_bounds__(256)
void rmsnorm_kernel(const float* __restrict__ x, const float* __restrict__ w,
                    float* __restrict__ o)
{
    const int row = blockIdx.x;
    const int tid = threadIdx.x;
    const float4 v = *(const float4*)(x + (size_t)row * D_ + tid * 4);
    float ss = v.x * v.x + v.y * v.y + v.z * v.z + v.w * v.w;
    #pragma unroll
    for (int off = 16; off; off >>= 1)
        ss += __shfl_xor_sync(0xffffffffu, ss, off);
    __shared__ float ws[8];
    __shared__ float s_inv;
    if ((tid & 31) == 0) ws[tid >> 5] = ss;
    __syncthreads();
    if (tid == 0) {
        float t = 0.f;
        #pragma unroll
        for (int i = 0; i < 8; i++) t += ws[i];
        s_inv = rsqrtf(t * (1.0f / D_) + 1e-5f);
    }
    __syncthreads();
    const float inv = s_inv;
    const float4 wv = *(const float4*)(w + tid * 4);
    float4 ov;
    ov.x = v.x * inv * wv.x;
    ov.y = v.y * inv * wv.y;
    ov.z = v.z * inv * wv.z;
    ov.w = v.w * inv * wv.w;
    *(float4*)(o + (size_t)row * D_ + tid * 4) = ov;
}

// ---------------------------------------------------------------------------
// SwiGLU gate (float4)
// ---------------------------------------------------------------------------
__global__ void silu_gate_kernel(float4* __restrict__ t1,
                                 const float4* __restrict__ t3, int n4)
{
    int i = blockIdx.x * blockDim.x + threadIdx.x;
    if (i < n4) {
        float4 a = t1[i];
        float4 b = t3[i];
        float4 o;
        o.x = (a.x / (1.f + __expf(-a.x))) * b.x;
        o.y = (a.y / (1.f + __expf(-a.y))) * b.y;
        o.z = (a.z / (1.f + __expf(-a.z))) * b.z;
        o.w = (a.w / (1.f + __expf(-a.w))) * b.w;
        t1[i] = o;
    }
}

// ---------------------------------------------------------------------------
// RoPE: rows of width 1024; position = posOff + (row % rowsMod)
// ---------------------------------------------------------------------------
__global__ void rope_kernel(float* __restrict__ t,
                            const float* __restrict__ cosT,
                            const float* __restrict__ sinT,
                            int rowsMod, int posOff, int nPairs)
{
    int id = blockIdx.x * blockDim.x + threadIdx.x;
    if (id >= nPairs) return;
    int pair = id & 511;
    int row  = id >> 9;
    int pos  = posOff + (row % rowsMod);
    int i    = pair & 31;
    float c = cosT[pos * 32 + i];
    float s = sinT[pos * 32 + i];
    float2* p = (float2*)(t + (size_t)row * D_ + pair * 2);
    float2 v = *p;
    float2 o;
    o.x = v.x * c - v.y * s;
    o.y = v.x * s + v.y * c;
    *p = o;
}

// ---------------------------------------------------------------------------
// Flash-style causal attention (x-part queries only).
// ---------------------------------------------------------------------------
#define ALD 65
#define ATTN_SMEM ((4 * 64 * ALD + 3 * 64) * (int)sizeof(float))

__global__ __launch_bounds__(256)
void attn_kernel(const float* __restrict__ Qx,
                 const float* __restrict__ Km, const float* __restrict__ Vm,
                 const float* __restrict__ Kx, const float* __restrict__ Vx,
                 float* __restrict__ Out, int sBase)
{
    extern __shared__ float sm[];
    float* Qs   = sm;
    float* Ks   = Qs + 64 * ALD;
    float* Vs   = Ks + 64 * ALD;
    float* Ss   = Vs + 64 * ALD;
    float* mrow = Ss + 64 * ALD;
    float* lrow = mrow + 64;
    float* crow = lrow + 64;

    const int b  = blockIdx.z;
    const int h  = blockIdx.y;
    const int qt = blockIdx.x;
    const int tid = threadIdx.x;
    const int tx = tid & 15, ty = tid >> 4;
    const int q0 = qt * 64;
    const float scale = 0.125f;

    for (int e = tid; e < 64 * 16; e += 256) {
        int i = e >> 4, d4 = (e & 15) * 4;
        float4 v = *(const float4*)&Qx[((size_t)(b * S_ + sBase + q0 + i)) * D_ + h * HD_ + d4];
        Qs[i * ALD + d4 + 0] = v.x;
        Qs[i * ALD + d4 + 1] = v.y;
        Qs[i * ALD + d4 + 2] = v.z;
        Qs[i * ALD + d4 + 3] = v.w;
    }
    if (tid < 64) { mrow[tid] = -1e30f; lrow[tid] = 0.f; }
    float acc[4][4];
    #pragma unroll
    for (int i = 0; i < 4; i++)
        #pragma unroll
        for (int j = 0; j < 4; j++) acc[i][j] = 0.f;
    __syncthreads();

    const int nkt = qt + 9;
    for (int kt = 0; kt < nkt; kt++) {
        const float* Kp;
        const float* Vp;
        size_t rb;
        if (kt < 8) {
            Kp = Km; Vp = Vm;
            rb = (size_t)(b * M_ + kt * 64);
        } else {
            Kp = Kx; Vp = Vx;
            rb = (size_t)(b * S_ + sBase + (kt - 8) * 64);
        }
        for (int e = tid; e < 64 * 16; e += 256) {
            int j = e >> 4, d4 = (e & 15) * 4;
            size_t base = (rb + j) * D_ + h * HD_ + d4;
            float4 kv = *(const float4*)&Kp[base];
            Ks[j * ALD + d4 + 0] = kv.x;
            Ks[j * ALD + d4 + 1] = kv.y;
            Ks[j * ALD + d4 + 2] = kv.z;
            Ks[j * ALD + d4 + 3] = kv.w;
            float4 vv = *(const float4*)&Vp[base];
            Vs[j * ALD + d4 + 0] = vv.x;
            Vs[j * ALD + d4 + 1] = vv.y;
            Vs[j * ALD + d4 + 2] = vv.z;
            Vs[j * ALD + d4 + 3] = vv.w;
        }
        __syncthreads();

        float s4[4][4];
        #pragma unroll
        for (int i = 0; i < 4; i++)
            #pragma unroll
            for (int j = 0; j < 4; j++) s4[i][j] = 0.f;
        for (int d = 0; d < 64; d++) {
            float rq[4], rk[4];
            #pragma unroll
            for (int ii = 0; ii < 4; ii++) rq[ii] = Qs[(ty * 4 + ii) * ALD + d];
            #pragma unroll
            for (int jj = 0; jj < 4; jj++) rk[jj] = Ks[(tx * 4 + jj) * ALD + d];
            #pragma unroll
            for (int ii = 0; ii < 4; ii++)
                #pragma unroll
                for (int jj = 0; jj < 4; jj++)
                    s4[ii][jj] = fmaf(rq[ii], rk[jj], s4[ii][jj]);
        }
        const int qg0 = M_ + q0;
        #pragma unroll
        for (int ii = 0; ii < 4; ii++) {
            int qi = qg0 + ty * 4 + ii;
            #pragma unroll
            for (int jj = 0; jj < 4; jj++) {
                int kj = kt * 64 + tx * 4 + jj;
                float val = (kj <= qi) ? s4[ii][jj] * scale : -1e30f;
                Ss[(ty * 4 + ii) * ALD + tx * 4 + jj] = val;
            }
        }
        __syncthreads();

        if (tid < 64) {
            float mold = mrow[tid];
            float mx = mold;
            for (int j = 0; j < 64; j++) mx = fmaxf(mx, Ss[tid * ALD + j]);
            float c = __expf(mold - mx);
            float sum = 0.f;
            for (int j = 0; j < 64; j++) {
                float p = __expf(Ss[tid * ALD + j] - mx);
                Ss[tid * ALD + j] = p;
                sum += p;
            }
            mrow[tid] = mx;
            lrow[tid] = lrow[tid] * c + sum;
            crow[tid] = c;
        }
        __syncthreads();

        float cc[4];
        #pragma unroll
        for (int ii = 0; ii < 4; ii++) cc[ii] = crow[ty * 4 + ii];
        #pragma unroll
        for (int ii = 0; ii < 4; ii++)
            #pragma unroll
            for (int dd = 0; dd < 4; dd++) acc[ii][dd] *= cc[ii];
        for (int j = 0; j < 64; j++) {
            float rp[4], rv[4];
            #pragma unroll
            for (int ii = 0; ii < 4; ii++) rp[ii] = Ss[(ty * 4 + ii) * ALD + j];
            #pragma unroll
            for (int dd = 0; dd < 4; dd++) rv[dd] = Vs[j * ALD + tx * 4 + dd];
            #pragma unroll
            for (int ii = 0; ii < 4; ii++)
                #pragma unroll
                for (int dd = 0; dd < 4; dd++)
                    acc[ii][dd] = fmaf(rp[ii], rv[dd], acc[ii][dd]);
        }
        __syncthreads();
    }

    if (tid < 64) crow[tid] = 1.f / lrow[tid];
    __syncthreads();
    #pragma unroll
    for (int ii = 0; ii < 4; ii++) {
        float inv = crow[ty * 4 + ii];
        int grow = b * S_ + sBase + q0 + ty * 4 + ii;
        float4 o;
        o.x = acc[ii][0] * inv;
        o.y = acc[ii][1] * inv;
        o.z = acc[ii][2] * inv;
        o.w = acc[ii][3] * inv;
        *(float4*)&Out[(size_t)grow * D_ + h * HD_ + tx * 4] = o;
    }
}

// ---------------------------------------------------------------------------
// Launch
// ---------------------------------------------------------------------------
extern "C" void kernel_launch(void* const* d_in, const int* in_sizes, int n_in,
                              void* d_out, int out_size)
{
    const float* x        = (const float*)d_in[0];
    const float* cosT     = (const float*)d_in[1];
    const float* sinT     = (const float*)d_in[2];
    const float* wq       = (const float*)d_in[3];
    const float* wk       = (const float*)d_in[4];
    const float* wv       = (const float*)d_in[5];
    const float* wo       = (const float*)d_in[6];
    const float* wm       = (const float*)d_in[7];
    const float* wkm      = (const float*)d_in[8];
    const float* wvm      = (const float*)d_in[9];
    const float* w1       = (const float*)d_in[10];
    const float* w3       = (const float*)d_in[11];
    const float* w2       = (const float*)d_in[12];
    const float* ffn_nw   = (const float*)d_in[13];
    const float* mem_nw   = (const float*)d_in[14];
    const float* omem     = (const float*)d_in[15];
    float* out = (float*)d_out;

    float *p_allout, *p_qx, *p_kx, *p_vx, *p_a, *p_hn, *p_t1, *p_t3, *p_m2, *p_k, *p_v;
    cudaGetSymbolAddress((void**)&p_allout, g_allout);
    cudaGetSymbolAddress((void**)&p_qx, g_qx);
    cudaGetSymbolAddress((void**)&p_kx, g_kx);
    cudaGetSymbolAddress((void**)&p_vx, g_vx);
    cudaGetSymbolAddress((void**)&p_a,  g_a);
    cudaGetSymbolAddress((void**)&p_hn, g_hn);
    cudaGetSymbolAddress((void**)&p_t1, g_t1);
    cudaGetSymbolAddress((void**)&p_t3, g_t3);
    cudaGetSymbolAddress((void**)&p_m2, g_m2);
    cudaGetSymbolAddress((void**)&p_k,  g_k);
    cudaGetSymbolAddress((void**)&p_v,  g_v);

    cudaFuncSetAttribute(attn_kernel,
                         cudaFuncAttributeMaxDynamicSharedMemorySize, ATTN_SMEM);

    const long long MD  = (long long)M_ * D_;
    const long long MH  = (long long)M_ * HID_;
    const long long SD  = (long long)S_ * D_;

    // ---- Upfront: all-step QKV projections + RoPE (independent of chain) ----
    mma_gemm_kernel<128, 128, false><<<dim3(24, 32, 2), 256, SMEM_OF(128, 128)>>>(
        x, SD, wq, wk, wv, p_qx, p_kx, p_vx, SD, SD, SD, D_, D_, 8);
    {
        int n = B_ * S_ * (D_ / 2);
        rope_kernel<<<(n + 255) / 256, 256>>>(p_qx, cosT, sinT, 512, M_, n);
        rope_kernel<<<(n + 255) / 256, 256>>>(p_kx, cosT, sinT, 512, M_, n);
    }

    // ---- Sequential memory chain ----
    for (int s = 0; s < NSTEP; s++) {
        const float* om = (s == 0) ? omem : (p_allout + (size_t)(s - 1) * M_ * D_);
        const long long omB = (s == 0) ? 0LL : SD;

        // a = om @ wm      (64x64 tiles: 256 CTAs)
        mma_gemm_kernel<64, 64, false><<<dim3(16, 8, 2), 256, SMEM_OF(64, 64)>>>(
            om, omB, wm, wm, wm, p_a, p_a, p_a, MD, MD, MD, D_, D_, 16);
        // hn = rmsnorm(a, ffn_norm_w)
        rmsnorm_kernel<<<B_ * M_, 256>>>(p_a, ffn_nw, p_hn);
        // t1 = hn @ w1 ; t3 = hn @ w3 (fused, 64x128: 704 CTAs)
        mma_gemm_kernel<64, 128, false><<<dim3(44, 8, 2), 256, SMEM_OF(64, 128)>>>(
            p_hn, MD, w1, w3, w3, p_t1, p_t3, p_t3, MH, MH, MH, D_, HID_, 22);
        // t1 = silu(t1) * t3
        silu_gate_kernel<<<(B_ * M_ * HID_ / 4 + 255) / 256, 256>>>(
            (float4*)p_t1, (const float4*)p_t3, B_ * M_ * HID_ / 4);
        // a += t1 @ w2     (64x64 tiles: 256 CTAs)
        mma_gemm_kernel<64, 64, true><<<dim3(16, 8, 2), 256, SMEM_OF(64, 64)>>>(
            p_t1, MH, w2, w2, w2, p_a, p_a, p_a, MD, MD, MD, HID_, D_, 16);
        // m2 = rmsnorm(a, mem_norm_w)
        rmsnorm_kernel<<<B_ * M_, 256>>>(p_a, mem_nw, p_m2);
        // mk, mv (fused, 64x128: 256 CTAs)
        mma_gemm_kernel<64, 128, false><<<dim3(16, 8, 2), 256, SMEM_OF(64, 128)>>>(
            p_m2, MD, wkm, wvm, wvm, p_k, p_v, p_v, MD, MD, MD, D_, D_, 8);
        // RoPE on mk (positions 0..511)
        {
            int n = B_ * M_ * (D_ / 2);
            rope_kernel<<<(n + 255) / 256, 256>>>(p_k, cosT, sinT, 512, 0, n);
        }
        // Attention
        attn_kernel<<<dim3(M_ / 64, H_, B_), 256, ATTN_SMEM>>>(
            p_qx, p_k, p_v, p_kx, p_vx, p_allout, s * M_);
    }

    // out = allout @ wo
    mma_gemm_kernel<128, 128, false><<<dim3(8, 64, 1), 256, SMEM_OF(128, 128)>>>(
        p_allout, 0LL, wo, wo, wo, out, out, out, 0LL, 0LL, 0LL, D_, D_, 8);
}